// round 7
// baseline (speedup 1.0000x reference)
#include <cuda_runtime.h>
#include <math.h>

#define HH 208
#define WW 336
#define NA 3
#define NPIX (HH*WW)            // 69888 per image
#define NPI (NPIX*NA)           // 209664 anchors per image
#define NB 2
#define PRE 2000
#define POST 1000
#define PRE_PAD 2048
#define CAND_CAP 4096
#define BBOX_CLIP 4.135166556742356f

// ---- output layout offsets (floats) ----
#define OFF_CLS   0
#define OFF_BBOX  (NB*NPIX*3)                // 419328
#define OFF_ROIS  (OFF_BBOX + NB*NPIX*12)    // 2096640
#define OFF_RSC   (OFF_ROIS + NB*POST*4)     // 2104640

// ---- device scratch ----
__device__ float              g_scores[NB][NPI];
__device__ float4             g_boxes[NB][NPI];
__device__ unsigned int       g_h16[NB][65536];     // zeroed at load; re-zeroed by compact_kernel
__device__ unsigned int       g_done;               // head completion ticket
__device__ int                g_pivot[NB];
__device__ int                g_cnt[NB];
__device__ unsigned long long g_cand[NB][CAND_CAP];
__device__ float              g_pre_scores[NB][PRE_PAD];
__device__ float4             g_pre_boxes[NB][PRE_PAD];
__device__ unsigned long long g_mask[NB][PRE_PAD][32];

// ---- f32x2 packed-math macros (sm_103a FFMA2) ----
#define FMA2(d, a, b)   asm("fma.rn.f32x2 %0, %1, %2, %0;" : "+l"(d) : "l"(a), "l"(b))
#define PACK2(d, x)     asm("mov.b64 %0, {%1, %1};" : "=l"(d) : "r"(__float_as_uint(x)))
#define UNPACK2(lo, hi, d) do { unsigned _l, _h; \
    asm("mov.b64 {%0, %1}, %2;" : "=r"(_l), "=r"(_h) : "l"(d)); \
    lo = __uint_as_float(_l); hi = __uint_as_float(_h); } while (0)

// ============================================================
// K1: fused 1x1 convs + sigmoid + decode + clip + histogram,
// and the LAST block computes the pivot bin (ticket pattern)
// ============================================================
#define TILE_P 512
#define PITCH  522

__global__ void __launch_bounds__(256) head_kernel(
        const float* __restrict__ feats,
        const float* __restrict__ img_info,
        const float* __restrict__ w_cls,
        const float* __restrict__ b_cls,
        const float* __restrict__ w_reg,
        const float* __restrict__ b_reg,
        float* __restrict__ out_cls,
        float* __restrict__ out_bbox) {
    __shared__ float sf[16 * PITCH];
    __shared__ __align__(16) float wsm[16 * 16];
    __shared__ unsigned int s_ticket;
    __shared__ unsigned int pwsum[8];

    int t = threadIdx.x;
    int p0 = blockIdx.x * TILE_P;
    const float4* f4 = (const float4*)feats;

    unsigned long long accA[8], accB[8];
#pragma unroll
    for (int q = 0; q < 8; q++) { accA[q] = 0ull; accB[q] = 0ull; }

    for (int cc = 0; cc < 16; cc++) {
        __syncthreads();
#pragma unroll
        for (int u = 0; u < 8; u++) {
            int idx = u*256 + t;
            int pl = idx >> 2, c4 = idx & 3;
            float4 v = f4[(size_t)(p0 + pl)*64 + cc*4 + c4];
            int cb = c4*4;
            sf[(cb+0)*PITCH + pl] = v.x;
            sf[(cb+1)*PITCH + pl] = v.y;
            sf[(cb+2)*PITCH + pl] = v.z;
            sf[(cb+3)*PITCH + pl] = v.w;
        }
        {
            int ch = t >> 4, o = t & 15;
            int cg = cc*16 + ch;
            float wv = (o < 3) ? w_cls[cg*3 + o] : (o < 15 ? w_reg[cg*12 + (o-3)] : 0.f);
            wsm[ch*16 + o] = wv;
        }
        __syncthreads();

#pragma unroll
        for (int cl = 0; cl < 16; cl++) {
            float fA = sf[cl*PITCH + t];
            float fB = sf[cl*PITCH + t + 256];
            unsigned long long fa2, fb2;
            PACK2(fa2, fA); PACK2(fb2, fB);
            const ulonglong2* wrow = (const ulonglong2*)(wsm + cl*16);
            ulonglong2 w01 = wrow[0], w23 = wrow[1], w45 = wrow[2], w67 = wrow[3];
            FMA2(accA[0], fa2, w01.x); FMA2(accA[1], fa2, w01.y);
            FMA2(accA[2], fa2, w23.x); FMA2(accA[3], fa2, w23.y);
            FMA2(accA[4], fa2, w45.x); FMA2(accA[5], fa2, w45.y);
            FMA2(accA[6], fa2, w67.x); FMA2(accA[7], fa2, w67.y);
            FMA2(accB[0], fb2, w01.x); FMA2(accB[1], fb2, w01.y);
            FMA2(accB[2], fb2, w23.x); FMA2(accB[3], fb2, w23.y);
            FMA2(accB[4], fb2, w45.x); FMA2(accB[5], fb2, w45.y);
            FMA2(accB[6], fb2, w67.x); FMA2(accB[7], fb2, w67.y);
        }
    }

    const float axs[3] = {1.0f, 1.4f, 0.7f};
    const float ays[3] = {1.0f, 0.7f, 1.4f};
#pragma unroll
    for (int px = 0; px < 2; px++) {
        int p = p0 + t + px*256;
        int b  = p / NPIX;
        int hw = p % NPIX;
        float f[16];
#pragma unroll
        for (int q = 0; q < 8; q++) {
            float lo, hi;
            UNPACK2(lo, hi, px ? accB[q] : accA[q]);
            f[2*q] = lo; f[2*q+1] = hi;
        }
        int h = hw / WW, w = hw % WW;
        float yc = (h + 0.5f) * 4.f;
        float xc = (w + 0.5f) * 4.f;
        float hmax = img_info[b*2 + 0];
        float wmax = img_info[b*2 + 1];
#pragma unroll
        for (int a = 0; a < 3; a++) {
            float cls = f[a] + b_cls[a];
            __stcs(&out_cls[((size_t)b*NPIX + hw)*3 + a], cls);
            float score = 1.f / (1.f + expf(-cls));
            int n = hw*3 + a;
            g_scores[b][n] = score;
            atomicAdd(&g_h16[b][__float_as_uint(score) >> 16], 1u);

            float dy = f[3 + a*4 + 0] + b_reg[a*4 + 0];
            float dx = f[3 + a*4 + 1] + b_reg[a*4 + 1];
            float dh = f[3 + a*4 + 2] + b_reg[a*4 + 2];
            float dw = f[3 + a*4 + 3] + b_reg[a*4 + 3];
            size_t bb = ((size_t)b*NPIX + hw)*12 + a*4;
            __stcs(&out_bbox[bb+0], dy); __stcs(&out_bbox[bb+1], dx);
            __stcs(&out_bbox[bb+2], dh); __stcs(&out_bbox[bb+3], dw);

            dh = fminf(fmaxf(dh, -BBOX_CLIP), BBOX_CLIP);
            dw = fminf(fmaxf(dw, -BBOX_CLIP), BBOX_CLIP);
            float ah = 32.f * ays[a], aw = 32.f * axs[a];
            float cy = dy*ah + yc, cx = dx*aw + xc;
            float hh2 = expf(dh)*ah, ww2 = expf(dw)*aw;
            float y1 = fminf(fmaxf(cy - 0.5f*hh2, 0.f), hmax);
            float x1 = fminf(fmaxf(cx - 0.5f*ww2, 0.f), wmax);
            float y2 = fminf(fmaxf(cy + 0.5f*hh2, 0.f), hmax);
            float x2 = fminf(fmaxf(cx + 0.5f*ww2, 0.f), wmax);
            g_boxes[b][n] = make_float4(y1, x1, y2, x2);
        }
    }

    // ---- ticket: last block to finish computes the pivot ----
    __threadfence();
    __syncthreads();
    if (t == 0) s_ticket = atomicAdd(&g_done, 1u);
    __syncthreads();
    if (s_ticket == gridDim.x - 1) {
        int lane = t & 31, warp = t >> 5;
        for (int b = 0; b < NB; b++) {
            const uint4* hv4 = (const uint4*)g_h16[b];
            unsigned sum = 0;
#pragma unroll
            for (int i = 0; i < 64; i++) {
                uint4 v = hv4[t*64 + i];
                sum += v.x + v.y + v.z + v.w;
            }
            unsigned suf = sum;
#pragma unroll
            for (int off = 1; off < 32; off <<= 1) {
                unsigned nv = __shfl_down_sync(0xffffffffu, suf, off);
                if (lane + off < 32) suf += nv;
            }
            if (lane == 0) pwsum[warp] = suf;
            __syncthreads();
            unsigned wab = 0;
            if (t == 0) {
                unsigned run = 0;
                for (int wz = 7; wz >= 0; wz--) {
                    unsigned tmp = pwsum[wz];
                    pwsum[wz] = run;          // sum of warps strictly after wz
                    run += tmp;
                }
            }
            __syncthreads();
            wab = pwsum[warp];
            unsigned sufT = suf + wab;
            unsigned above = sufT - sum;
            if (sufT >= (unsigned)PRE && above < (unsigned)PRE) {
                unsigned cum = above;
                const uint4* base = hv4 + t*64;
                int pivot = t*256;
                for (int g = 63; g >= 0; g--) {
                    uint4 v = base[g];
                    unsigned s4 = v.x + v.y + v.z + v.w;
                    if (cum + s4 >= (unsigned)PRE) {
                        if      (cum + v.w >= (unsigned)PRE)             pivot = t*256 + 4*g + 3;
                        else if (cum + v.w + v.z >= (unsigned)PRE)       pivot = t*256 + 4*g + 2;
                        else if (cum + v.w + v.z + v.y >= (unsigned)PRE) pivot = t*256 + 4*g + 1;
                        else                                              pivot = t*256 + 4*g;
                        break;
                    }
                    cum += s4;
                }
                g_pivot[b] = pivot;
                g_cnt[b] = 0;
            }
            __syncthreads();
        }
        if (t == 0) g_done = 0;
    }
}

// ============================================================
// K2: grid-wide compaction (bin >= pivot) + histogram re-zero
// ============================================================
__global__ void compact_kernel() {
    int t = threadIdx.x;
    int zid = blockIdx.x * 256 + t;        // 512*256 == 2*65536 exactly
    g_h16[zid >> 16][zid & 65535] = 0;

    int stride = gridDim.x * blockDim.x;
    int gid = blockIdx.x * blockDim.x + t;
#pragma unroll
    for (int b = 0; b < NB; b++) {
        int P = g_pivot[b];
        for (int n = gid; n < NPI; n += stride) {
            unsigned key = __float_as_uint(g_scores[b][n]);
            if ((int)(key >> 16) >= P) {
                int slot = atomicAdd(&g_cnt[b], 1);
                if (slot < CAND_CAP)
                    g_cand[b][slot] =
                        ((unsigned long long)key << 32) | (unsigned)(~(unsigned)n);
            }
        }
    }
}

// ============================================================
// K3: rank-by-counting scatter (exact sorted order, no sort)
// grid = NB*4 blocks x 1024; thread-per-candidate, keys in smem
// ============================================================
__global__ void __launch_bounds__(1024, 1) rank_kernel() {
    __shared__ unsigned long long s[CAND_CAP];
    int blk = blockIdx.x;
    int b = blk >> 2, part = blk & 3;
    int t = threadIdx.x;
    int C = min(g_cnt[b], CAND_CAP);

    for (int i = t; i < CAND_CAP; i += 1024)
        s[i] = (i < C) ? g_cand[b][i] : 0ull;
    __syncthreads();

    int idx = part*1024 + t;
    if (idx < C) {
        unsigned long long k = s[idx];
        int r = 0;
        for (int j = 0; j < C; j++) r += (s[j] > k);   // broadcast LDS, all keys distinct
        if (r < PRE_PAD) {
            unsigned nn = ~(unsigned)(k & 0xffffffffull);
            g_pre_boxes[b][r]  = g_boxes[b][nn];
            g_pre_scores[b][r] = __uint_as_float((unsigned)(k >> 32));
        }
    }
}

// ============================================================
// K4: pairwise suppression mask (upper triangle of word-columns)
// ============================================================
__global__ void mask_kernel() {
    __shared__ float4 jb[PRE_PAD];
    __shared__ float  ca[PRE_PAD];
    int blk = blockIdx.x;
    int b = blk >> 6;
    int r = blk & 63;
    int it = r >> 1;
    int half = r & 1;
    int t = threadIdx.x;

    for (int i = t; i < PRE_PAD; i += 256) {
        float4 bx = g_pre_boxes[b][i];
        jb[i] = bx;
        ca[i] = 0.41176470588f * (bx.z - bx.x) * (bx.w - bx.y);  // 0.7/1.7 * area
    }
    __syncthreads();

    int lane = t & 31;
    int i = it*64 + half*32 + lane;
    float4 bi = jb[i];
    float cai = ca[i] + 4.1176e-9f;
    int nwords = 32 - it;
    for (int wq = t >> 5; wq < nwords; wq += 8) {
        int w = it + wq;
        int j0 = w * 64;
        unsigned long long m = 0;
#pragma unroll
        for (int bit = 0; bit < 64; bit++) {
            float4 bj = jb[j0 + bit];
            float y1 = fmaxf(bi.x, bj.x), x1 = fmaxf(bi.y, bj.y);
            float y2 = fminf(bi.z, bj.z), x2 = fminf(bi.w, bj.w);
            float inter = fmaxf(y2 - y1, 0.f) * fmaxf(x2 - x1, 0.f);
            if (inter > cai + ca[j0 + bit]) m |= (1ull << bit);
        }
        g_mask[b][i][w] = m;
    }
}

// ============================================================
// K5: chunked bitmask scan, 2 barriers/chunk, double-buffered diag
// ============================================================
__global__ void __launch_bounds__(1024, 1) nms_scan(float* __restrict__ out_rois,
                                                    float* __restrict__ out_rscores) {
    __shared__ unsigned long long removed[32];
    __shared__ unsigned long long sIntra[2][64];
    __shared__ unsigned long long partial[32][33];
    __shared__ short kept[POST + 8];
    __shared__ int s_kc, s_k0, s_nk;

    int b = blockIdx.x, t = threadIdx.x;
    if (t < 32) removed[t] = 0ull;
    if (t == 0) s_kc = 0;
    if (t < 64) sIntra[0][t] = g_mask[b][t][0];
    __syncthreads();

    for (int c = 0; c < 32; c++) {
        if (s_kc >= POST) break;                      // uniform (post-sync)
        int cur = c & 1;
        // incremental fold of last iteration's partials into words >= c
        if (c > 0 && t >= c && t < 32) {
            unsigned long long v = removed[t];
#pragma unroll
            for (int g2 = 0; g2 < 32; g2++) v |= partial[g2][t];
            removed[t] = v;
        }
        if (t == c) {                                 // greedy on chunk c (owner thread)
            unsigned long long R = removed[c];
            int k = s_kc;
            s_k0 = k;
            int lim = min(64, PRE - c*64);
#pragma unroll
            for (int base = 0; base < 64; base += 8) {
                unsigned long long si[8];
#pragma unroll
                for (int u = 0; u < 8; u++) si[u] = sIntra[cur][base + u];
#pragma unroll
                for (int u = 0; u < 8; u++) {
                    int bit = base + u;
                    int keep = (bit < lim) & (k < POST) & (int)(~(R >> bit) & 1ull);
                    kept[k] = (short)(c*64 + bit);
                    R |= keep ? si[u] : 0ull;
                    k += keep;
                }
            }
            s_kc = k;
            s_nk = k - s_k0;
        }
        __syncthreads();
        // prefetch next chunk's diagonal words (overlaps the OR loads)
        if (t < 64 && c < 31) sIntra[cur ^ 1][t] = g_mask[b][(c+1)*64 + t][c+1];
        int w = t & 31, g = t >> 5;
        unsigned long long acc = 0ull;
        int nk = s_nk, k0 = s_k0;
        if (w > c) {
            for (int rr = g; rr < nk; rr += 32)
                acc |= g_mask[b][(int)kept[k0 + rr]][w];
        }
        partial[g][w] = acc;
        __syncthreads();
    }
    __syncthreads();

    int kc = s_kc;
    for (int i = t; i < POST; i += 1024) {
        float4 bo; float sc;
        if (i < kc) { int j = kept[i]; bo = g_pre_boxes[b][j]; sc = g_pre_scores[b][j]; }
        else        { bo = g_pre_boxes[b][0]; sc = -1.f; }
        size_t o = ((size_t)b*POST + i) * 4;
        out_rois[o+0] = bo.x; out_rois[o+1] = bo.y;
        out_rois[o+2] = bo.z; out_rois[o+3] = bo.w;
        out_rscores[(size_t)b*POST + i] = sc;
    }
}

// ============================================================
extern "C" void kernel_launch(void* const* d_in, const int* in_sizes, int n_in,
                              void* d_out, int out_size) {
    const float* feats    = (const float*)d_in[0];
    const float* img_info = (const float*)d_in[1];
    const float* w_cls    = (const float*)d_in[2];
    const float* b_cls    = (const float*)d_in[3];
    const float* w_reg    = (const float*)d_in[4];
    const float* b_reg    = (const float*)d_in[5];
    float* out = (float*)d_out;

    float* out_cls  = out + OFF_CLS;
    float* out_bbox = out + OFF_BBOX;
    float* out_rois = out + OFF_ROIS;
    float* out_rsc  = out + OFF_RSC;

    head_kernel<<<(NB*NPIX)/TILE_P, 256>>>(feats, img_info, w_cls, b_cls, w_reg, b_reg,
                                           out_cls, out_bbox);
    compact_kernel<<<512, 256>>>();
    rank_kernel<<<NB*4, 1024>>>();
    mask_kernel<<<NB*64, 256>>>();
    nms_scan<<<NB, 1024>>>(out_rois, out_rsc);
}

// round 8
// speedup vs baseline: 1.0006x; 1.0006x over previous
#include <cuda_runtime.h>
#include <math.h>

#define HH 208
#define WW 336
#define NA 3
#define NPIX (HH*WW)            // 69888 per image
#define NPI (NPIX*NA)           // 209664 anchors per image
#define NB 2
#define PRE 2000
#define POST 1000
#define PRE_PAD 2048
#define CAND_CAP 4096
#define BBOX_CLIP 4.135166556742356f

// ---- output layout offsets (floats) ----
#define OFF_CLS   0
#define OFF_BBOX  (NB*NPIX*3)                // 419328
#define OFF_ROIS  (OFF_BBOX + NB*NPIX*12)    // 2096640
#define OFF_RSC   (OFF_ROIS + NB*POST*4)     // 2104640

// ---- device scratch ----
__device__ float              g_scores[NB][NPI];
__device__ float4             g_boxes[NB][NPI];
__device__ unsigned int       g_h16[NB][65536];     // zeroed at load; re-zeroed by compact_kernel
__device__ int                g_pivot[NB];
__device__ int                g_cnt[NB];
__device__ unsigned long long g_cand[NB][CAND_CAP];
__device__ float              g_pre_scores[NB][PRE_PAD];
__device__ float4             g_pre_boxes[NB][PRE_PAD];
__device__ unsigned long long g_mask[NB][PRE_PAD][32];

// ---- f32x2 packed-math macros (sm_103a FFMA2) ----
#define FMA2(d, a, b)   asm("fma.rn.f32x2 %0, %1, %2, %0;" : "+l"(d) : "l"(a), "l"(b))
#define PACK2(d, x)     asm("mov.b64 %0, {%1, %1};" : "=l"(d) : "r"(__float_as_uint(x)))
#define UNPACK2(lo, hi, d) do { unsigned _l, _h; \
    asm("mov.b64 {%0, %1}, %2;" : "=r"(_l), "=r"(_h) : "l"(d)); \
    lo = __uint_as_float(_l); hi = __uint_as_float(_h); } while (0)

// ============================================================
// K1: fused 1x1 convs + sigmoid + decode + clip + score histogram
// (exact R5 structure)
// ============================================================
#define TILE_P 512
#define PITCH  522

__global__ void __launch_bounds__(256) head_kernel(
        const float* __restrict__ feats,
        const float* __restrict__ img_info,
        const float* __restrict__ w_cls,
        const float* __restrict__ b_cls,
        const float* __restrict__ w_reg,
        const float* __restrict__ b_reg,
        float* __restrict__ out_cls,
        float* __restrict__ out_bbox) {
    __shared__ float sf[16 * PITCH];
    __shared__ __align__(16) float wsm[16 * 16];

    int t = threadIdx.x;
    int p0 = blockIdx.x * TILE_P;
    const float4* f4 = (const float4*)feats;

    unsigned long long accA[8], accB[8];
#pragma unroll
    for (int q = 0; q < 8; q++) { accA[q] = 0ull; accB[q] = 0ull; }

    for (int cc = 0; cc < 16; cc++) {
        __syncthreads();
#pragma unroll
        for (int u = 0; u < 8; u++) {
            int idx = u*256 + t;
            int pl = idx >> 2, c4 = idx & 3;
            float4 v = f4[(size_t)(p0 + pl)*64 + cc*4 + c4];
            int cb = c4*4;
            sf[(cb+0)*PITCH + pl] = v.x;
            sf[(cb+1)*PITCH + pl] = v.y;
            sf[(cb+2)*PITCH + pl] = v.z;
            sf[(cb+3)*PITCH + pl] = v.w;
        }
        {
            int ch = t >> 4, o = t & 15;
            int cg = cc*16 + ch;
            float wv = (o < 3) ? w_cls[cg*3 + o] : (o < 15 ? w_reg[cg*12 + (o-3)] : 0.f);
            wsm[ch*16 + o] = wv;
        }
        __syncthreads();

#pragma unroll
        for (int cl = 0; cl < 16; cl++) {
            float fA = sf[cl*PITCH + t];
            float fB = sf[cl*PITCH + t + 256];
            unsigned long long fa2, fb2;
            PACK2(fa2, fA); PACK2(fb2, fB);
            const ulonglong2* wrow = (const ulonglong2*)(wsm + cl*16);
            ulonglong2 w01 = wrow[0], w23 = wrow[1], w45 = wrow[2], w67 = wrow[3];
            FMA2(accA[0], fa2, w01.x); FMA2(accA[1], fa2, w01.y);
            FMA2(accA[2], fa2, w23.x); FMA2(accA[3], fa2, w23.y);
            FMA2(accA[4], fa2, w45.x); FMA2(accA[5], fa2, w45.y);
            FMA2(accA[6], fa2, w67.x); FMA2(accA[7], fa2, w67.y);
            FMA2(accB[0], fb2, w01.x); FMA2(accB[1], fb2, w01.y);
            FMA2(accB[2], fb2, w23.x); FMA2(accB[3], fb2, w23.y);
            FMA2(accB[4], fb2, w45.x); FMA2(accB[5], fb2, w45.y);
            FMA2(accB[6], fb2, w67.x); FMA2(accB[7], fb2, w67.y);
        }
    }

    const float axs[3] = {1.0f, 1.4f, 0.7f};
    const float ays[3] = {1.0f, 0.7f, 1.4f};
#pragma unroll
    for (int px = 0; px < 2; px++) {
        int p = p0 + t + px*256;
        int b  = p / NPIX;
        int hw = p % NPIX;
        float f[16];
#pragma unroll
        for (int q = 0; q < 8; q++) {
            float lo, hi;
            UNPACK2(lo, hi, px ? accB[q] : accA[q]);
            f[2*q] = lo; f[2*q+1] = hi;
        }
        int h = hw / WW, w = hw % WW;
        float yc = (h + 0.5f) * 4.f;
        float xc = (w + 0.5f) * 4.f;
        float hmax = img_info[b*2 + 0];
        float wmax = img_info[b*2 + 1];
#pragma unroll
        for (int a = 0; a < 3; a++) {
            float cls = f[a] + b_cls[a];
            __stcs(&out_cls[((size_t)b*NPIX + hw)*3 + a], cls);
            float score = 1.f / (1.f + expf(-cls));
            int n = hw*3 + a;
            g_scores[b][n] = score;
            atomicAdd(&g_h16[b][__float_as_uint(score) >> 16], 1u);

            float dy = f[3 + a*4 + 0] + b_reg[a*4 + 0];
            float dx = f[3 + a*4 + 1] + b_reg[a*4 + 1];
            float dh = f[3 + a*4 + 2] + b_reg[a*4 + 2];
            float dw = f[3 + a*4 + 3] + b_reg[a*4 + 3];
            size_t bb = ((size_t)b*NPIX + hw)*12 + a*4;
            __stcs(&out_bbox[bb+0], dy); __stcs(&out_bbox[bb+1], dx);
            __stcs(&out_bbox[bb+2], dh); __stcs(&out_bbox[bb+3], dw);

            dh = fminf(fmaxf(dh, -BBOX_CLIP), BBOX_CLIP);
            dw = fminf(fmaxf(dw, -BBOX_CLIP), BBOX_CLIP);
            float ah = 32.f * ays[a], aw = 32.f * axs[a];
            float cy = dy*ah + yc, cx = dx*aw + xc;
            float hh2 = expf(dh)*ah, ww2 = expf(dw)*aw;
            float y1 = fminf(fmaxf(cy - 0.5f*hh2, 0.f), hmax);
            float x1 = fminf(fmaxf(cx - 0.5f*ww2, 0.f), wmax);
            float y2 = fminf(fmaxf(cy + 0.5f*hh2, 0.f), hmax);
            float x2 = fminf(fmaxf(cx + 0.5f*ww2, 0.f), wmax);
            g_boxes[b][n] = make_float4(y1, x1, y2, x2);
        }
    }
}

// ============================================================
// K2: pivot-bin search (R5 shfl hierarchical suffix scan)
// ============================================================
__global__ void __launch_bounds__(1024, 1) scan_kernel() {
    __shared__ unsigned int wabove[32];
    int b = blockIdx.x, t = threadIdx.x;
    int lane = t & 31, warp = t >> 5;
    const uint4* hv4 = (const uint4*)g_h16[b];
    unsigned sum = 0;
#pragma unroll
    for (int i = 0; i < 16; i++) {
        uint4 v = hv4[t*16 + i];
        sum += v.x + v.y + v.z + v.w;
    }
    unsigned suf = sum;
#pragma unroll
    for (int off = 1; off < 32; off <<= 1) {
        unsigned n = __shfl_down_sync(0xffffffffu, suf, off);
        if (lane + off < 32) suf += n;
    }
    if (lane == 0) wabove[warp] = suf;
    __syncthreads();
    if (warp == 0) {
        unsigned ws = wabove[lane];
        unsigned wsuf = ws;
#pragma unroll
        for (int off = 1; off < 32; off <<= 1) {
            unsigned n = __shfl_down_sync(0xffffffffu, wsuf, off);
            if (lane + off < 32) wsuf += n;
        }
        wabove[lane] = wsuf - ws;
    }
    __syncthreads();
    unsigned sufT = suf + wabove[warp];
    unsigned above = sufT - sum;
    if (sufT >= (unsigned)PRE && above < (unsigned)PRE) {
        unsigned cum = above;
        int pivot = t*64;
        const unsigned* hb = g_h16[b] + t*64;
        for (int j = 63; j >= 0; j--) {
            cum += hb[j];
            if (cum >= (unsigned)PRE) { pivot = t*64 + j; break; }
        }
        g_pivot[b] = pivot;
        g_cnt[b] = 0;
    }
}

// ============================================================
// K3: grid-wide compaction (bin >= pivot) + histogram re-zero
// ============================================================
__global__ void compact_kernel() {
    int t = threadIdx.x;
    int zid = blockIdx.x * 256 + t;        // 512*256 == 2*65536 exactly
    g_h16[zid >> 16][zid & 65535] = 0;

    int stride = gridDim.x * blockDim.x;
    int gid = blockIdx.x * blockDim.x + t;
#pragma unroll
    for (int b = 0; b < NB; b++) {
        int P = g_pivot[b];
        for (int n = gid; n < NPI; n += stride) {
            unsigned key = __float_as_uint(g_scores[b][n]);
            if ((int)(key >> 16) >= P) {
                int slot = atomicAdd(&g_cnt[b], 1);
                if (slot < CAND_CAP)
                    g_cand[b][slot] =
                        ((unsigned long long)key << 32) | (unsigned)(~(unsigned)n);
            }
        }
    }
}

// ============================================================
// K4: rank-by-counting scatter (exact sorted order, no sort)
// grid = NB*4 blocks x 1024; thread-per-candidate, keys in smem.
// Slots [C, 2048) are never written and remain zero (== old padding).
// ============================================================
__global__ void __launch_bounds__(1024, 1) rank_kernel() {
    __shared__ unsigned long long s[CAND_CAP];
    int blk = blockIdx.x;
    int b = blk >> 2, part = blk & 3;
    int t = threadIdx.x;
    int C = min(g_cnt[b], CAND_CAP);

    for (int i = t; i < CAND_CAP; i += 1024)
        s[i] = (i < C) ? g_cand[b][i] : 0ull;
    __syncthreads();

    int idx = part*1024 + t;
    if (idx < C) {
        unsigned long long k = s[idx];
        int r = 0;
        int j = 0;
        for (; j + 4 <= C; j += 4) {
            r += (s[j] > k) + (s[j+1] > k) + (s[j+2] > k) + (s[j+3] > k);
        }
        for (; j < C; j++) r += (s[j] > k);
        if (r < PRE_PAD) {
            unsigned nn = ~(unsigned)(k & 0xffffffffull);
            g_pre_boxes[b][r]  = g_boxes[b][nn];
            g_pre_scores[b][r] = __uint_as_float((unsigned)(k >> 32));
        }
    }
}

// ============================================================
// K5: pairwise suppression mask — 512 threads (16 warps) per block
// ============================================================
__global__ void __launch_bounds__(512) mask_kernel() {
    __shared__ float4 jb[PRE_PAD];
    __shared__ float  ca[PRE_PAD];
    int blk = blockIdx.x;
    int b = blk >> 6;
    int r = blk & 63;
    int it = r >> 1;
    int half = r & 1;
    int t = threadIdx.x;

    for (int i = t; i < PRE_PAD; i += 512) {
        float4 bx = g_pre_boxes[b][i];
        jb[i] = bx;
        ca[i] = 0.41176470588f * (bx.z - bx.x) * (bx.w - bx.y);  // 0.7/1.7 * area
    }
    __syncthreads();

    int lane = t & 31;
    int i = it*64 + half*32 + lane;
    float4 bi = jb[i];
    float cai = ca[i] + 4.1176e-9f;
    int nwords = 32 - it;
    for (int wq = t >> 5; wq < nwords; wq += 16) {
        int w = it + wq;
        int j0 = w * 64;
        unsigned long long m = 0;
#pragma unroll
        for (int bit = 0; bit < 64; bit++) {
            float4 bj = jb[j0 + bit];
            float y1 = fmaxf(bi.x, bj.x), x1 = fmaxf(bi.y, bj.y);
            float y2 = fminf(bi.z, bj.z), x2 = fminf(bi.w, bj.w);
            float inter = fmaxf(y2 - y1, 0.f) * fmaxf(x2 - x1, 0.f);
            if (inter > cai + ca[j0 + bit]) m |= (1ull << bit);
        }
        g_mask[b][i][w] = m;
    }
}

// ============================================================
// K6: chunked bitmask scan (R5 version, 3 barriers/chunk)
// ============================================================
__global__ void __launch_bounds__(1024, 1) nms_scan(float* __restrict__ out_rois,
                                                    float* __restrict__ out_rscores) {
    __shared__ unsigned long long removed[32];
    __shared__ unsigned long long sIntra[64];
    __shared__ unsigned long long partial[32][33];
    __shared__ short kept[POST + 8];
    __shared__ int s_kc, s_k0, s_nk;

    int b = blockIdx.x, t = threadIdx.x;
    if (t < 32) removed[t] = 0ull;
    if (t == 0) s_kc = 0;

    for (int c = 0; c < 32; c++) {
        __syncthreads();
        if (s_kc >= POST) break;                       // uniform
        if (t < 64) sIntra[t] = g_mask[b][c*64 + t][c];
        __syncthreads();
        if (t == 0) {
            unsigned long long R = removed[c];
            int k = s_kc;
            s_k0 = k;
            int lim = min(64, PRE - c*64);
#pragma unroll
            for (int base = 0; base < 64; base += 8) {
                unsigned long long si[8];
#pragma unroll
                for (int u = 0; u < 8; u++) si[u] = sIntra[base + u];
#pragma unroll
                for (int u = 0; u < 8; u++) {
                    int bit = base + u;
                    int keep = (bit < lim) & (k < POST) & (int)(~(R >> bit) & 1ull);
                    kept[k] = (short)(c*64 + bit);
                    R |= keep ? si[u] : 0ull;
                    k += keep;
                }
            }
            s_kc = k;
            s_nk = k - s_k0;
        }
        __syncthreads();
        int w = t & 31, g = t >> 5;
        unsigned long long acc = 0ull;
        int nk = s_nk, k0 = s_k0;
        if (w > c) {
            for (int rr = g; rr < nk; rr += 32)
                acc |= g_mask[b][(int)kept[k0 + rr]][w];
        }
        partial[g][w] = acc;
        __syncthreads();
        if (t < 32 && t > c) {
            unsigned long long vv = removed[t];
#pragma unroll
            for (int g2 = 0; g2 < 32; g2++) vv |= partial[g2][t];
            removed[t] = vv;
        }
    }
    __syncthreads();

    int kc = s_kc;
    for (int i = t; i < POST; i += 1024) {
        float4 bo; float sc;
        if (i < kc) { int j = kept[i]; bo = g_pre_boxes[b][j]; sc = g_pre_scores[b][j]; }
        else        { bo = g_pre_boxes[b][0]; sc = -1.f; }
        size_t o = ((size_t)b*POST + i) * 4;
        out_rois[o+0] = bo.x; out_rois[o+1] = bo.y;
        out_rois[o+2] = bo.z; out_rois[o+3] = bo.w;
        out_rscores[(size_t)b*POST + i] = sc;
    }
}

// ============================================================
extern "C" void kernel_launch(void* const* d_in, const int* in_sizes, int n_in,
                              void* d_out, int out_size) {
    const float* feats    = (const float*)d_in[0];
    const float* img_info = (const float*)d_in[1];
    const float* w_cls    = (const float*)d_in[2];
    const float* b_cls    = (const float*)d_in[3];
    const float* w_reg    = (const float*)d_in[4];
    const float* b_reg    = (const float*)d_in[5];
    float* out = (float*)d_out;

    float* out_cls  = out + OFF_CLS;
    float* out_bbox = out + OFF_BBOX;
    float* out_rois = out + OFF_ROIS;
    float* out_rsc  = out + OFF_RSC;

    head_kernel<<<(NB*NPIX)/TILE_P, 256>>>(feats, img_info, w_cls, b_cls, w_reg, b_reg,
                                           out_cls, out_bbox);
    scan_kernel<<<NB, 1024>>>();
    compact_kernel<<<512, 256>>>();
    rank_kernel<<<NB*4, 1024>>>();
    mask_kernel<<<NB*64, 512>>>();
    nms_scan<<<NB, 1024>>>(out_rois, out_rsc);
}

// round 9
// speedup vs baseline: 1.2668x; 1.2661x over previous
#include <cuda_runtime.h>
#include <math.h>

#define HH 208
#define WW 336
#define NA 3
#define NPIX (HH*WW)            // 69888 per image
#define NPI (NPIX*NA)           // 209664 anchors per image
#define NB 2
#define PRE 2000
#define POST 1000
#define PRE_PAD 2048
#define CAND_CAP 4096
#define BBOX_CLIP 4.135166556742356f

// ---- output layout offsets (floats) ----
#define OFF_CLS   0
#define OFF_BBOX  (NB*NPIX*3)                // 419328
#define OFF_ROIS  (OFF_BBOX + NB*NPIX*12)    // 2096640
#define OFF_RSC   (OFF_ROIS + NB*POST*4)     // 2104640

// ---- device scratch ----
__device__ float              g_scores[NB][NPI];
__device__ float4             g_boxes[NB][NPI];
__device__ unsigned int       g_h16[NB][65536];     // zeroed at load; re-zeroed by compact_kernel
__device__ int                g_pivot[NB];
__device__ int                g_cnt[NB];
__device__ unsigned long long g_cand[NB][CAND_CAP];
__device__ float              g_pre_scores[NB][PRE_PAD];
__device__ float4             g_pre_boxes[NB][PRE_PAD];
__device__ unsigned long long g_mask[NB][PRE_PAD][32];

// ---- f32x2 packed-math macros (sm_103a FFMA2) ----
#define FMA2(d, a, b)   asm("fma.rn.f32x2 %0, %1, %2, %0;" : "+l"(d) : "l"(a), "l"(b))
#define PACK2(d, x)     asm("mov.b64 %0, {%1, %1};" : "=l"(d) : "r"(__float_as_uint(x)))
#define UNPACK2(lo, hi, d) do { unsigned _l, _h; \
    asm("mov.b64 {%0, %1}, %2;" : "=r"(_l), "=r"(_h) : "l"(d)); \
    lo = __uint_as_float(_l); hi = __uint_as_float(_h); } while (0)

// ============================================================
// K1: fused 1x1 convs + sigmoid + decode + clip + score histogram
// ============================================================
#define TILE_P 512
#define PITCH  522

__global__ void __launch_bounds__(256) head_kernel(
        const float* __restrict__ feats,
        const float* __restrict__ img_info,
        const float* __restrict__ w_cls,
        const float* __restrict__ b_cls,
        const float* __restrict__ w_reg,
        const float* __restrict__ b_reg,
        float* __restrict__ out_cls,
        float* __restrict__ out_bbox) {
    __shared__ float sf[16 * PITCH];
    __shared__ __align__(16) float wsm[16 * 16];

    int t = threadIdx.x;
    int p0 = blockIdx.x * TILE_P;
    const float4* f4 = (const float4*)feats;

    unsigned long long accA[8], accB[8];
#pragma unroll
    for (int q = 0; q < 8; q++) { accA[q] = 0ull; accB[q] = 0ull; }

    for (int cc = 0; cc < 16; cc++) {
        __syncthreads();
#pragma unroll
        for (int u = 0; u < 8; u++) {
            int idx = u*256 + t;
            int pl = idx >> 2, c4 = idx & 3;
            float4 v = f4[(size_t)(p0 + pl)*64 + cc*4 + c4];
            int cb = c4*4;
            sf[(cb+0)*PITCH + pl] = v.x;
            sf[(cb+1)*PITCH + pl] = v.y;
            sf[(cb+2)*PITCH + pl] = v.z;
            sf[(cb+3)*PITCH + pl] = v.w;
        }
        {
            int ch = t >> 4, o = t & 15;
            int cg = cc*16 + ch;
            float wv = (o < 3) ? w_cls[cg*3 + o] : (o < 15 ? w_reg[cg*12 + (o-3)] : 0.f);
            wsm[ch*16 + o] = wv;
        }
        __syncthreads();

#pragma unroll
        for (int cl = 0; cl < 16; cl++) {
            float fA = sf[cl*PITCH + t];
            float fB = sf[cl*PITCH + t + 256];
            unsigned long long fa2, fb2;
            PACK2(fa2, fA); PACK2(fb2, fB);
            const ulonglong2* wrow = (const ulonglong2*)(wsm + cl*16);
            ulonglong2 w01 = wrow[0], w23 = wrow[1], w45 = wrow[2], w67 = wrow[3];
            FMA2(accA[0], fa2, w01.x); FMA2(accA[1], fa2, w01.y);
            FMA2(accA[2], fa2, w23.x); FMA2(accA[3], fa2, w23.y);
            FMA2(accA[4], fa2, w45.x); FMA2(accA[5], fa2, w45.y);
            FMA2(accA[6], fa2, w67.x); FMA2(accA[7], fa2, w67.y);
            FMA2(accB[0], fb2, w01.x); FMA2(accB[1], fb2, w01.y);
            FMA2(accB[2], fb2, w23.x); FMA2(accB[3], fb2, w23.y);
            FMA2(accB[4], fb2, w45.x); FMA2(accB[5], fb2, w45.y);
            FMA2(accB[6], fb2, w67.x); FMA2(accB[7], fb2, w67.y);
        }
    }

    const float axs[3] = {1.0f, 1.4f, 0.7f};
    const float ays[3] = {1.0f, 0.7f, 1.4f};
#pragma unroll
    for (int px = 0; px < 2; px++) {
        int p = p0 + t + px*256;
        int b  = p / NPIX;
        int hw = p % NPIX;
        float f[16];
#pragma unroll
        for (int q = 0; q < 8; q++) {
            float lo, hi;
            UNPACK2(lo, hi, px ? accB[q] : accA[q]);
            f[2*q] = lo; f[2*q+1] = hi;
        }
        int h = hw / WW, w = hw % WW;
        float yc = (h + 0.5f) * 4.f;
        float xc = (w + 0.5f) * 4.f;
        float hmax = img_info[b*2 + 0];
        float wmax = img_info[b*2 + 1];
#pragma unroll
        for (int a = 0; a < 3; a++) {
            float cls = f[a] + b_cls[a];
            __stcs(&out_cls[((size_t)b*NPIX + hw)*3 + a], cls);
            float score = 1.f / (1.f + expf(-cls));
            int n = hw*3 + a;
            g_scores[b][n] = score;
            atomicAdd(&g_h16[b][__float_as_uint(score) >> 16], 1u);

            float dy = f[3 + a*4 + 0] + b_reg[a*4 + 0];
            float dx = f[3 + a*4 + 1] + b_reg[a*4 + 1];
            float dh = f[3 + a*4 + 2] + b_reg[a*4 + 2];
            float dw = f[3 + a*4 + 3] + b_reg[a*4 + 3];
            size_t bb = ((size_t)b*NPIX + hw)*12 + a*4;
            __stcs(&out_bbox[bb+0], dy); __stcs(&out_bbox[bb+1], dx);
            __stcs(&out_bbox[bb+2], dh); __stcs(&out_bbox[bb+3], dw);

            dh = fminf(fmaxf(dh, -BBOX_CLIP), BBOX_CLIP);
            dw = fminf(fmaxf(dw, -BBOX_CLIP), BBOX_CLIP);
            float ah = 32.f * ays[a], aw = 32.f * axs[a];
            float cy = dy*ah + yc, cx = dx*aw + xc;
            float hh2 = expf(dh)*ah, ww2 = expf(dw)*aw;
            float y1 = fminf(fmaxf(cy - 0.5f*hh2, 0.f), hmax);
            float x1 = fminf(fmaxf(cx - 0.5f*ww2, 0.f), wmax);
            float y2 = fminf(fmaxf(cy + 0.5f*hh2, 0.f), hmax);
            float x2 = fminf(fmaxf(cx + 0.5f*ww2, 0.f), wmax);
            g_boxes[b][n] = make_float4(y1, x1, y2, x2);
        }
    }
}

// ============================================================
// K2: pivot-bin search (shfl hierarchical suffix scan)
// ============================================================
__global__ void __launch_bounds__(1024, 1) scan_kernel() {
    __shared__ unsigned int wabove[32];
    int b = blockIdx.x, t = threadIdx.x;
    int lane = t & 31, warp = t >> 5;
    const uint4* hv4 = (const uint4*)g_h16[b];
    unsigned sum = 0;
#pragma unroll
    for (int i = 0; i < 16; i++) {
        uint4 v = hv4[t*16 + i];
        sum += v.x + v.y + v.z + v.w;
    }
    unsigned suf = sum;
#pragma unroll
    for (int off = 1; off < 32; off <<= 1) {
        unsigned n = __shfl_down_sync(0xffffffffu, suf, off);
        if (lane + off < 32) suf += n;
    }
    if (lane == 0) wabove[warp] = suf;
    __syncthreads();
    if (warp == 0) {
        unsigned ws = wabove[lane];
        unsigned wsuf = ws;
#pragma unroll
        for (int off = 1; off < 32; off <<= 1) {
            unsigned n = __shfl_down_sync(0xffffffffu, wsuf, off);
            if (lane + off < 32) wsuf += n;
        }
        wabove[lane] = wsuf - ws;
    }
    __syncthreads();
    unsigned sufT = suf + wabove[warp];
    unsigned above = sufT - sum;
    if (sufT >= (unsigned)PRE && above < (unsigned)PRE) {
        unsigned cum = above;
        int pivot = t*64;
        const unsigned* hb = g_h16[b] + t*64;
        for (int j = 63; j >= 0; j--) {
            cum += hb[j];
            if (cum >= (unsigned)PRE) { pivot = t*64 + j; break; }
        }
        g_pivot[b] = pivot;
        g_cnt[b] = 0;
    }
}

// ============================================================
// K3: grid-wide compaction (bin >= pivot) + histogram re-zero
// ============================================================
__global__ void compact_kernel() {
    int t = threadIdx.x;
    int zid = blockIdx.x * 256 + t;        // 512*256 == 2*65536 exactly
    g_h16[zid >> 16][zid & 65535] = 0;

    int stride = gridDim.x * blockDim.x;
    int gid = blockIdx.x * blockDim.x + t;
#pragma unroll
    for (int b = 0; b < NB; b++) {
        int P = g_pivot[b];
        for (int n = gid; n < NPI; n += stride) {
            unsigned key = __float_as_uint(g_scores[b][n]);
            if ((int)(key >> 16) >= P) {
                int slot = atomicAdd(&g_cnt[b], 1);
                if (slot < CAND_CAP)
                    g_cand[b][slot] =
                        ((unsigned long long)key << 32) | (unsigned)(~(unsigned)n);
            }
        }
    }
}

// ============================================================
// K4: 2-D rank-by-counting scatter (exact sorted order, no sort)
// grid = NB*64 blocks x 1024; 16 threads per candidate, 64 cands/block.
// rank = #{keys > mine}; keys distinct -> exact top_k order.
// Slots [C, 2048) never written, remain zero (== old padding).
// ============================================================
__global__ void __launch_bounds__(1024, 1) rank_kernel() {
    __shared__ unsigned long long s[CAND_CAP];
    int blk = blockIdx.x;
    int b = blk >> 6, part = blk & 63;
    int t = threadIdx.x;
    int C = min(g_cnt[b], CAND_CAP);

    int cand = part*64 + (t >> 4);      // this thread's candidate index
    if (part*64 >= C) return;           // whole block idle

    for (int i = t; i < C; i += 1024) s[i] = g_cand[b][i];
    __syncthreads();

    unsigned long long k = (cand < C) ? s[cand] : 0ull;
    int stripe = t & 15;
    int r = 0;
    for (int j = stripe; j < C; j += 16) r += (s[j] > k);
    // reduce 16 partial counts (width-16 shuffle tree)
#pragma unroll
    for (int off = 8; off >= 1; off >>= 1)
        r += __shfl_down_sync(0xffffffffu, r, off, 16);

    if (stripe == 0 && cand < C && r < PRE_PAD) {
        unsigned nn = ~(unsigned)(k & 0xffffffffull);
        g_pre_boxes[b][r]  = g_boxes[b][nn];
        g_pre_scores[b][r] = __uint_as_float((unsigned)(k >> 32));
    }
}

// ============================================================
// K5: pairwise suppression mask — 512 threads (16 warps) per block
// ============================================================
__global__ void __launch_bounds__(512) mask_kernel() {
    __shared__ float4 jb[PRE_PAD];
    __shared__ float  ca[PRE_PAD];
    int blk = blockIdx.x;
    int b = blk >> 6;
    int r = blk & 63;
    int it = r >> 1;
    int half = r & 1;
    int t = threadIdx.x;

    for (int i = t; i < PRE_PAD; i += 512) {
        float4 bx = g_pre_boxes[b][i];
        jb[i] = bx;
        ca[i] = 0.41176470588f * (bx.z - bx.x) * (bx.w - bx.y);  // 0.7/1.7 * area
    }
    __syncthreads();

    int lane = t & 31;
    int i = it*64 + half*32 + lane;
    float4 bi = jb[i];
    float cai = ca[i] + 4.1176e-9f;
    int nwords = 32 - it;
    for (int wq = t >> 5; wq < nwords; wq += 16) {
        int w = it + wq;
        int j0 = w * 64;
        unsigned long long m = 0;
#pragma unroll
        for (int bit = 0; bit < 64; bit++) {
            float4 bj = jb[j0 + bit];
            float y1 = fmaxf(bi.x, bj.x), x1 = fmaxf(bi.y, bj.y);
            float y2 = fminf(bi.z, bj.z), x2 = fminf(bi.w, bj.w);
            float inter = fmaxf(y2 - y1, 0.f) * fmaxf(x2 - x1, 0.f);
            if (inter > cai + ca[j0 + bit]) m |= (1ull << bit);
        }
        g_mask[b][i][w] = m;
    }
}

// ============================================================
// K6: chunked bitmask scan (exact greedy NMS order) + output
// ============================================================
__global__ void __launch_bounds__(1024, 1) nms_scan(float* __restrict__ out_rois,
                                                    float* __restrict__ out_rscores) {
    __shared__ unsigned long long removed[32];
    __shared__ unsigned long long sIntra[64];
    __shared__ unsigned long long partial[32][33];
    __shared__ short kept[POST + 8];
    __shared__ int s_kc, s_k0, s_nk;

    int b = blockIdx.x, t = threadIdx.x;
    if (t < 32) removed[t] = 0ull;
    if (t == 0) s_kc = 0;

    for (int c = 0; c < 32; c++) {
        __syncthreads();
        if (s_kc >= POST) break;                       // uniform
        if (t < 64) sIntra[t] = g_mask[b][c*64 + t][c];
        __syncthreads();
        if (t == 0) {
            unsigned long long R = removed[c];
            int k = s_kc;
            s_k0 = k;
            int lim = min(64, PRE - c*64);
#pragma unroll
            for (int base = 0; base < 64; base += 8) {
                unsigned long long si[8];
#pragma unroll
                for (int u = 0; u < 8; u++) si[u] = sIntra[base + u];
#pragma unroll
                for (int u = 0; u < 8; u++) {
                    int bit = base + u;
                    int keep = (bit < lim) & (k < POST) & (int)(~(R >> bit) & 1ull);
                    kept[k] = (short)(c*64 + bit);
                    R |= keep ? si[u] : 0ull;
                    k += keep;
                }
            }
            s_kc = k;
            s_nk = k - s_k0;
        }
        __syncthreads();
        int w = t & 31, g = t >> 5;
        unsigned long long acc = 0ull;
        int nk = s_nk, k0 = s_k0;
        if (w > c) {
            for (int rr = g; rr < nk; rr += 32)
                acc |= g_mask[b][(int)kept[k0 + rr]][w];
        }
        partial[g][w] = acc;
        __syncthreads();
        if (t < 32 && t > c) {
            unsigned long long vv = removed[t];
#pragma unroll
            for (int g2 = 0; g2 < 32; g2++) vv |= partial[g2][t];
            removed[t] = vv;
        }
    }
    __syncthreads();

    int kc = s_kc;
    for (int i = t; i < POST; i += 1024) {
        float4 bo; float sc;
        if (i < kc) { int j = kept[i]; bo = g_pre_boxes[b][j]; sc = g_pre_scores[b][j]; }
        else        { bo = g_pre_boxes[b][0]; sc = -1.f; }
        size_t o = ((size_t)b*POST + i) * 4;
        out_rois[o+0] = bo.x; out_rois[o+1] = bo.y;
        out_rois[o+2] = bo.z; out_rois[o+3] = bo.w;
        out_rscores[(size_t)b*POST + i] = sc;
    }
}

// ============================================================
extern "C" void kernel_launch(void* const* d_in, const int* in_sizes, int n_in,
                              void* d_out, int out_size) {
    const float* feats    = (const float*)d_in[0];
    const float* img_info = (const float*)d_in[1];
    const float* w_cls    = (const float*)d_in[2];
    const float* b_cls    = (const float*)d_in[3];
    const float* w_reg    = (const float*)d_in[4];
    const float* b_reg    = (const float*)d_in[5];
    float* out = (float*)d_out;

    float* out_cls  = out + OFF_CLS;
    float* out_bbox = out + OFF_BBOX;
    float* out_rois = out + OFF_ROIS;
    float* out_rsc  = out + OFF_RSC;

    head_kernel<<<(NB*NPIX)/TILE_P, 256>>>(feats, img_info, w_cls, b_cls, w_reg, b_reg,
                                           out_cls, out_bbox);
    scan_kernel<<<NB, 1024>>>();
    compact_kernel<<<512, 256>>>();
    rank_kernel<<<NB*64, 1024>>>();
    mask_kernel<<<NB*64, 512>>>();
    nms_scan<<<NB, 1024>>>(out_rois, out_rsc);
}

// round 10
// speedup vs baseline: 1.3084x; 1.0328x over previous
#include <cuda_runtime.h>
#include <math.h>

#define HH 208
#define WW 336
#define NA 3
#define NPIX (HH*WW)            // 69888 per image
#define NPI (NPIX*NA)           // 209664 anchors per image
#define NB 2
#define PRE 2000
#define POST 1000
#define PRE_PAD 2048
#define CAND_CAP 4096
#define BBOX_CLIP 4.135166556742356f

// ---- output layout offsets (floats) ----
#define OFF_CLS   0
#define OFF_BBOX  (NB*NPIX*3)                // 419328
#define OFF_ROIS  (OFF_BBOX + NB*NPIX*12)    // 2096640
#define OFF_RSC   (OFF_ROIS + NB*POST*4)     // 2104640

// ---- device scratch ----
__device__ float              g_scores[NB][NPI];
__device__ unsigned int       g_h16[NB][65536];     // zeroed at load; re-zeroed by compact_kernel
__device__ int                g_pivot[NB];
__device__ int                g_cnt[NB];
__device__ unsigned long long g_cand[NB][CAND_CAP];
__device__ float              g_pre_scores[NB][PRE_PAD];
__device__ float4             g_pre_boxes[NB][PRE_PAD];
__device__ unsigned long long g_mask[NB][PRE_PAD][32];

// ---- f32x2 packed-math macros (sm_103a FFMA2) ----
#define FMA2(d, a, b)   asm("fma.rn.f32x2 %0, %1, %2, %0;" : "+l"(d) : "l"(a), "l"(b))
#define PACK2(d, x)     asm("mov.b64 %0, {%1, %1};" : "=l"(d) : "r"(__float_as_uint(x)))
#define UNPACK2(lo, hi, d) do { unsigned _l, _h; \
    asm("mov.b64 {%0, %1}, %2;" : "=r"(_l), "=r"(_h) : "l"(d)); \
    lo = __uint_as_float(_l); hi = __uint_as_float(_h); } while (0)

// ============================================================
// K1: fused 1x1 convs + sigmoid + score histogram + raw bbox store
// (decode/clip moved OUT — only candidates get decoded, in rank)
// ============================================================
#define TILE_P 512
#define PITCH  522

__global__ void __launch_bounds__(256) head_kernel(
        const float* __restrict__ feats,
        const float* __restrict__ w_cls,
        const float* __restrict__ b_cls,
        const float* __restrict__ w_reg,
        const float* __restrict__ b_reg,
        float* __restrict__ out_cls,
        float* __restrict__ out_bbox) {
    __shared__ float sf[16 * PITCH];
    __shared__ __align__(16) float wsm[16 * 16];

    int t = threadIdx.x;
    int p0 = blockIdx.x * TILE_P;
    const float4* f4 = (const float4*)feats;

    unsigned long long accA[8], accB[8];
#pragma unroll
    for (int q = 0; q < 8; q++) { accA[q] = 0ull; accB[q] = 0ull; }

    for (int cc = 0; cc < 16; cc++) {
        __syncthreads();
#pragma unroll
        for (int u = 0; u < 8; u++) {
            int idx = u*256 + t;
            int pl = idx >> 2, c4 = idx & 3;
            float4 v = f4[(size_t)(p0 + pl)*64 + cc*4 + c4];
            int cb = c4*4;
            sf[(cb+0)*PITCH + pl] = v.x;
            sf[(cb+1)*PITCH + pl] = v.y;
            sf[(cb+2)*PITCH + pl] = v.z;
            sf[(cb+3)*PITCH + pl] = v.w;
        }
        {
            int ch = t >> 4, o = t & 15;
            int cg = cc*16 + ch;
            float wv = (o < 3) ? w_cls[cg*3 + o] : (o < 15 ? w_reg[cg*12 + (o-3)] : 0.f);
            wsm[ch*16 + o] = wv;
        }
        __syncthreads();

#pragma unroll
        for (int cl = 0; cl < 16; cl++) {
            float fA = sf[cl*PITCH + t];
            float fB = sf[cl*PITCH + t + 256];
            unsigned long long fa2, fb2;
            PACK2(fa2, fA); PACK2(fb2, fB);
            const ulonglong2* wrow = (const ulonglong2*)(wsm + cl*16);
            ulonglong2 w01 = wrow[0], w23 = wrow[1], w45 = wrow[2], w67 = wrow[3];
            FMA2(accA[0], fa2, w01.x); FMA2(accA[1], fa2, w01.y);
            FMA2(accA[2], fa2, w23.x); FMA2(accA[3], fa2, w23.y);
            FMA2(accA[4], fa2, w45.x); FMA2(accA[5], fa2, w45.y);
            FMA2(accA[6], fa2, w67.x); FMA2(accA[7], fa2, w67.y);
            FMA2(accB[0], fb2, w01.x); FMA2(accB[1], fb2, w01.y);
            FMA2(accB[2], fb2, w23.x); FMA2(accB[3], fb2, w23.y);
            FMA2(accB[4], fb2, w45.x); FMA2(accB[5], fb2, w45.y);
            FMA2(accB[6], fb2, w67.x); FMA2(accB[7], fb2, w67.y);
        }
    }

#pragma unroll
    for (int px = 0; px < 2; px++) {
        int p = p0 + t + px*256;
        int b  = p / NPIX;
        int hw = p % NPIX;
        float f[16];
#pragma unroll
        for (int q = 0; q < 8; q++) {
            float lo, hi;
            UNPACK2(lo, hi, px ? accB[q] : accA[q]);
            f[2*q] = lo; f[2*q+1] = hi;
        }
#pragma unroll
        for (int a = 0; a < 3; a++) {
            float cls = f[a] + b_cls[a];
            __stcs(&out_cls[((size_t)b*NPIX + hw)*3 + a], cls);
            float score = 1.f / (1.f + expf(-cls));
            int n = hw*3 + a;
            g_scores[b][n] = score;
            atomicAdd(&g_h16[b][__float_as_uint(score) >> 16], 1u);

            float dy = f[3 + a*4 + 0] + b_reg[a*4 + 0];
            float dx = f[3 + a*4 + 1] + b_reg[a*4 + 1];
            float dh = f[3 + a*4 + 2] + b_reg[a*4 + 2];
            float dw = f[3 + a*4 + 3] + b_reg[a*4 + 3];
            size_t bb = ((size_t)b*NPIX + hw)*12 + a*4;
            __stcs(&out_bbox[bb+0], dy); __stcs(&out_bbox[bb+1], dx);
            __stcs(&out_bbox[bb+2], dh); __stcs(&out_bbox[bb+3], dw);
        }
    }
}

// ============================================================
// K2: pivot-bin search (shfl hierarchical suffix scan)
// ============================================================
__global__ void __launch_bounds__(1024, 1) scan_kernel() {
    __shared__ unsigned int wabove[32];
    int b = blockIdx.x, t = threadIdx.x;
    int lane = t & 31, warp = t >> 5;
    const uint4* hv4 = (const uint4*)g_h16[b];
    unsigned sum = 0;
#pragma unroll
    for (int i = 0; i < 16; i++) {
        uint4 v = hv4[t*16 + i];
        sum += v.x + v.y + v.z + v.w;
    }
    unsigned suf = sum;
#pragma unroll
    for (int off = 1; off < 32; off <<= 1) {
        unsigned n = __shfl_down_sync(0xffffffffu, suf, off);
        if (lane + off < 32) suf += n;
    }
    if (lane == 0) wabove[warp] = suf;
    __syncthreads();
    if (warp == 0) {
        unsigned ws = wabove[lane];
        unsigned wsuf = ws;
#pragma unroll
        for (int off = 1; off < 32; off <<= 1) {
            unsigned n = __shfl_down_sync(0xffffffffu, wsuf, off);
            if (lane + off < 32) wsuf += n;
        }
        wabove[lane] = wsuf - ws;
    }
    __syncthreads();
    unsigned sufT = suf + wabove[warp];
    unsigned above = sufT - sum;
    if (sufT >= (unsigned)PRE && above < (unsigned)PRE) {
        unsigned cum = above;
        int pivot = t*64;
        const unsigned* hb = g_h16[b] + t*64;
        for (int j = 63; j >= 0; j--) {
            cum += hb[j];
            if (cum >= (unsigned)PRE) { pivot = t*64 + j; break; }
        }
        g_pivot[b] = pivot;
        g_cnt[b] = 0;
    }
}

// ============================================================
// K3: grid-wide compaction (bin >= pivot) + histogram re-zero
// ============================================================
__global__ void compact_kernel() {
    int t = threadIdx.x;
    int zid = blockIdx.x * 256 + t;        // 512*256 == 2*65536 exactly
    g_h16[zid >> 16][zid & 65535] = 0;

    int stride = gridDim.x * blockDim.x;
    int gid = blockIdx.x * blockDim.x + t;
#pragma unroll
    for (int b = 0; b < NB; b++) {
        int P = g_pivot[b];
        for (int n = gid; n < NPI; n += stride) {
            unsigned key = __float_as_uint(g_scores[b][n]);
            if ((int)(key >> 16) >= P) {
                int slot = atomicAdd(&g_cnt[b], 1);
                if (slot < CAND_CAP)
                    g_cand[b][slot] =
                        ((unsigned long long)key << 32) | (unsigned)(~(unsigned)n);
            }
        }
    }
}

// ============================================================
// K4: 2-D rank-by-counting scatter + on-the-fly decode/clip
// grid = NB*64 blocks x 1024; 16 threads/candidate, 64 cands/block.
// Only the <=2048 winning threads decode their box.
// ============================================================
__global__ void __launch_bounds__(1024, 1) rank_kernel(
        const float* __restrict__ out_bbox,
        const float* __restrict__ img_info) {
    __shared__ unsigned long long s[CAND_CAP];
    int blk = blockIdx.x;
    int b = blk >> 6, part = blk & 63;
    int t = threadIdx.x;
    int C = min(g_cnt[b], CAND_CAP);

    int cand = part*64 + (t >> 4);
    if (part*64 >= C) return;

    for (int i = t; i < C; i += 1024) s[i] = g_cand[b][i];
    __syncthreads();

    unsigned long long k = (cand < C) ? s[cand] : 0ull;
    int stripe = t & 15;
    int r = 0;
    for (int j = stripe; j < C; j += 16) r += (s[j] > k);
#pragma unroll
    for (int off = 8; off >= 1; off >>= 1)
        r += __shfl_down_sync(0xffffffffu, r, off, 16);

    if (stripe == 0 && cand < C && r < PRE_PAD) {
        unsigned nn = ~(unsigned)(k & 0xffffffffull);
        int hw = nn / 3, a = nn % 3;
        int h = hw / WW, w = hw % WW;
        const float4* d4 = (const float4*)(out_bbox + ((size_t)b*NPIX + hw)*12 + a*4);
        float4 d = *d4;                       // (dy, dx, dh, dw), bias included
        float dy = d.x, dx = d.y;
        float dh = fminf(fmaxf(d.z, -BBOX_CLIP), BBOX_CLIP);
        float dw = fminf(fmaxf(d.w, -BBOX_CLIP), BBOX_CLIP);
        const float axs[3] = {1.0f, 1.4f, 0.7f};
        const float ays[3] = {1.0f, 0.7f, 1.4f};
        float ah = 32.f * ays[a], aw = 32.f * axs[a];
        float yc = (h + 0.5f) * 4.f, xc = (w + 0.5f) * 4.f;
        float hmax = img_info[b*2 + 0], wmax = img_info[b*2 + 1];
        float cy = dy*ah + yc, cx = dx*aw + xc;
        float hh2 = expf(dh)*ah, ww2 = expf(dw)*aw;
        float y1 = fminf(fmaxf(cy - 0.5f*hh2, 0.f), hmax);
        float x1 = fminf(fmaxf(cx - 0.5f*ww2, 0.f), wmax);
        float y2 = fminf(fmaxf(cy + 0.5f*hh2, 0.f), hmax);
        float x2 = fminf(fmaxf(cx + 0.5f*ww2, 0.f), wmax);
        g_pre_boxes[b][r]  = make_float4(y1, x1, y2, x2);
        g_pre_scores[b][r] = __uint_as_float((unsigned)(k >> 32));
    }
}

// ============================================================
// K5: pairwise suppression mask — 512 threads (16 warps) per block
// ============================================================
__global__ void __launch_bounds__(512) mask_kernel() {
    __shared__ float4 jb[PRE_PAD];
    __shared__ float  ca[PRE_PAD];
    int blk = blockIdx.x;
    int b = blk >> 6;
    int r = blk & 63;
    int it = r >> 1;
    int half = r & 1;
    int t = threadIdx.x;

    for (int i = t; i < PRE_PAD; i += 512) {
        float4 bx = g_pre_boxes[b][i];
        jb[i] = bx;
        ca[i] = 0.41176470588f * (bx.z - bx.x) * (bx.w - bx.y);  // 0.7/1.7 * area
    }
    __syncthreads();

    int lane = t & 31;
    int i = it*64 + half*32 + lane;
    float4 bi = jb[i];
    float cai = ca[i] + 4.1176e-9f;
    int nwords = 32 - it;
    for (int wq = t >> 5; wq < nwords; wq += 16) {
        int w = it + wq;
        int j0 = w * 64;
        unsigned long long m = 0;
#pragma unroll
        for (int bit = 0; bit < 64; bit++) {
            float4 bj = jb[j0 + bit];
            float y1 = fmaxf(bi.x, bj.x), x1 = fmaxf(bi.y, bj.y);
            float y2 = fminf(bi.z, bj.z), x2 = fminf(bi.w, bj.w);
            float inter = fmaxf(y2 - y1, 0.f) * fmaxf(x2 - x1, 0.f);
            if (inter > cai + ca[j0 + bit]) m |= (1ull << bit);
        }
        g_mask[b][i][w] = m;
    }
}

// ============================================================
// K6: chunked bitmask scan (exact greedy NMS order) + output
// ============================================================
__global__ void __launch_bounds__(1024, 1) nms_scan(float* __restrict__ out_rois,
                                                    float* __restrict__ out_rscores) {
    __shared__ unsigned long long removed[32];
    __shared__ unsigned long long sIntra[64];
    __shared__ unsigned long long partial[32][33];
    __shared__ short kept[POST + 8];
    __shared__ int s_kc, s_k0, s_nk;

    int b = blockIdx.x, t = threadIdx.x;
    if (t < 32) removed[t] = 0ull;
    if (t == 0) s_kc = 0;

    for (int c = 0; c < 32; c++) {
        __syncthreads();
        if (s_kc >= POST) break;                       // uniform
        if (t < 64) sIntra[t] = g_mask[b][c*64 + t][c];
        __syncthreads();
        if (t == 0) {
            unsigned long long R = removed[c];
            int k = s_kc;
            s_k0 = k;
            int lim = min(64, PRE - c*64);
#pragma unroll
            for (int base = 0; base < 64; base += 8) {
                unsigned long long si[8];
#pragma unroll
                for (int u = 0; u < 8; u++) si[u] = sIntra[base + u];
#pragma unroll
                for (int u = 0; u < 8; u++) {
                    int bit = base + u;
                    int keep = (bit < lim) & (k < POST) & (int)(~(R >> bit) & 1ull);
                    kept[k] = (short)(c*64 + bit);
                    R |= keep ? si[u] : 0ull;
                    k += keep;
                }
            }
            s_kc = k;
            s_nk = k - s_k0;
        }
        __syncthreads();
        int w = t & 31, g = t >> 5;
        unsigned long long acc = 0ull;
        int nk = s_nk, k0 = s_k0;
        if (w > c) {
            for (int rr = g; rr < nk; rr += 32)
                acc |= g_mask[b][(int)kept[k0 + rr]][w];
        }
        partial[g][w] = acc;
        __syncthreads();
        if (t < 32 && t > c) {
            unsigned long long vv = removed[t];
#pragma unroll
            for (int g2 = 0; g2 < 32; g2++) vv |= partial[g2][t];
            removed[t] = vv;
        }
    }
    __syncthreads();

    int kc = s_kc;
    for (int i = t; i < POST; i += 1024) {
        float4 bo; float sc;
        if (i < kc) { int j = kept[i]; bo = g_pre_boxes[b][j]; sc = g_pre_scores[b][j]; }
        else        { bo = g_pre_boxes[b][0]; sc = -1.f; }
        size_t o = ((size_t)b*POST + i) * 4;
        out_rois[o+0] = bo.x; out_rois[o+1] = bo.y;
        out_rois[o+2] = bo.z; out_rois[o+3] = bo.w;
        out_rscores[(size_t)b*POST + i] = sc;
    }
}

// ============================================================
extern "C" void kernel_launch(void* const* d_in, const int* in_sizes, int n_in,
                              void* d_out, int out_size) {
    const float* feats    = (const float*)d_in[0];
    const float* img_info = (const float*)d_in[1];
    const float* w_cls    = (const float*)d_in[2];
    const float* b_cls    = (const float*)d_in[3];
    const float* w_reg    = (const float*)d_in[4];
    const float* b_reg    = (const float*)d_in[5];
    float* out = (float*)d_out;

    float* out_cls  = out + OFF_CLS;
    float* out_bbox = out + OFF_BBOX;
    float* out_rois = out + OFF_ROIS;
    float* out_rsc  = out + OFF_RSC;

    head_kernel<<<(NB*NPIX)/TILE_P, 256>>>(feats, w_cls, b_cls, w_reg, b_reg,
                                           out_cls, out_bbox);
    scan_kernel<<<NB, 1024>>>();
    compact_kernel<<<512, 256>>>();
    rank_kernel<<<NB*64, 1024>>>(out_bbox, img_info);
    mask_kernel<<<NB*64, 512>>>();
    nms_scan<<<NB, 1024>>>(out_rois, out_rsc);
}